// round 1
// baseline (speedup 1.0000x reference)
#include <cuda_runtime.h>

#define N_SRC0 500000
#define N_DST0 100000
#define E0     1000000
#define N_DST1 10000
#define E1     100000
#define N_DST2 1024
#define E2     10240
#define D      128
#define NCLS   47

// ---------------- scratch (static device globals; no allocation) ----------------
__device__ float g_agg0[N_DST0 * D];
__device__ float g_h0  [N_DST0 * D];
__device__ float g_agg1[N_DST1 * D];
__device__ float g_h1  [N_DST1 * D];
__device__ float g_agg2[N_DST2 * D];
__device__ int   g_outdeg1[N_DST0];
__device__ int   g_indeg1 [N_DST1];
__device__ int   g_outdeg2[N_DST1];
__device__ int   g_indeg2 [N_DST2];

// ---------------- zero kernels ----------------
__global__ void zero_agg0_k() {
    int i = blockIdx.x * blockDim.x + threadIdx.x;
    if (i < N_DST0 * D / 4) ((float4*)g_agg0)[i] = make_float4(0.f, 0.f, 0.f, 0.f);
}

__global__ void zero_aux_k() {
    int i = blockIdx.x * blockDim.x + threadIdx.x;
    int stride = gridDim.x * blockDim.x;
    const int n1 = N_DST1 * D / 4;   // agg1 float4 count
    const int n2 = N_DST2 * D / 4;   // agg2 float4 count
    for (int j = i; j < n1 + n2; j += stride) {
        if (j < n1) ((float4*)g_agg1)[j] = make_float4(0.f, 0.f, 0.f, 0.f);
        else        ((float4*)g_agg2)[j - n1] = make_float4(0.f, 0.f, 0.f, 0.f);
    }
    const int ndeg = N_DST0 + N_DST1 + N_DST1 + N_DST2;
    for (int j = i; j < ndeg; j += stride) {
        if      (j < N_DST0)                    g_outdeg1[j] = 0;
        else if (j < N_DST0 + N_DST1)           g_indeg1 [j - N_DST0] = 0;
        else if (j < N_DST0 + 2 * N_DST1)       g_outdeg2[j - N_DST0 - N_DST1] = 0;
        else                                    g_indeg2 [j - N_DST0 - 2 * N_DST1] = 0;
    }
}

// ---------------- degree counting (layers 1 & 2) ----------------
__global__ void deg_k(const int* __restrict__ s1, const int* __restrict__ d1,
                      const int* __restrict__ s2, const int* __restrict__ d2) {
    int t = blockIdx.x * blockDim.x + threadIdx.x;
    if (t < E1) {
        atomicAdd(&g_outdeg1[s1[t]], 1);
        atomicAdd(&g_indeg1 [d1[t]], 1);
    }
    if (t < E2) {
        atomicAdd(&g_outdeg2[s2[t]], 1);
        atomicAdd(&g_indeg2 [d2[t]], 1);
    }
}

// ---------------- edge scatter: one warp per edge, vec4 reductions ----------------
__global__ void scatter_k(const float* __restrict__ feat, const int* __restrict__ src,
                          const int* __restrict__ dst, float* __restrict__ agg, int E) {
    int gt = blockIdx.x * blockDim.x + threadIdx.x;
    int e = gt >> 5;
    int lane = gt & 31;
    if (e >= E) return;
    int s = src[e];
    int d = dst[e];
    float4 v = ((const float4*)feat)[s * 32 + lane];
    float* p = agg + (long)d * D + lane * 4;
    asm volatile("red.global.add.v4.f32 [%0], {%1,%2,%3,%4};"
                 :: "l"(p), "f"(v.x), "f"(v.y), "f"(v.z), "f"(v.w) : "memory");
}

// ---------------- tiled 128x128xK=128 fp32 GEMM with fused epilogue ----------------
// out[r] = relu( pre(r) * (A[rowmap(r)] @ W) + bias ) * post(r)
// rowmap: optional composed permutation inv[shuf[r]] (layer 0 only)
// pre   : optional rsqrt(max(pre_deg[r],1))   (in-degree norm, applied before bias)
// post  : optional rsqrt(max(post_deg[r],1))  (NEXT layer's out-degree norm, folded)
__global__ __launch_bounds__(256) void gemm_k(
    const float* __restrict__ A, const float* __restrict__ W, const float* __restrict__ bias,
    const int* __restrict__ invp, const int* __restrict__ shufp,
    const int* __restrict__ pre_deg, const int* __restrict__ post_deg,
    float* __restrict__ out, int M)
{
    extern __shared__ float sm[];
    float (*As)[132] = (float(*)[132])sm;                 // 128 x 132 (padded)
    float (*Ws)[128] = (float(*)[128])(sm + 128 * 132);   // 128 x 128 (k-major, as stored)

    int t = threadIdx.x;
    int r0 = blockIdx.x * 128;

    // load W (16384 floats = 4096 float4)
    float4* wsv = (float4*)(sm + 128 * 132);
#pragma unroll
    for (int i = 0; i < 16; i++) {
        int idx = t + 256 * i;
        wsv[idx] = ((const float4*)W)[idx];
    }
    // load A tile rows (row-major in smem; coalesced gmem float4)
#pragma unroll
    for (int i = 0; i < 16; i++) {
        int lin = t + 256 * i;
        int m = lin >> 5;      // tile row 0..127
        int kq = lin & 31;     // float4 index along k
        int r = r0 + m;
        float4 v = make_float4(0.f, 0.f, 0.f, 0.f);
        if (r < M) {
            int rs = r;
            if (invp) rs = invp[shufp[r]];
            v = ((const float4*)A)[rs * 32 + kq];
        }
        *(float4*)&As[m][kq * 4] = v;
    }
    __syncthreads();

    int tx = t & 15, ty = t >> 4;
    int c0 = tx * 8, m0 = ty * 8;

    float acc[8][8];
#pragma unroll
    for (int i = 0; i < 8; i++)
#pragma unroll
        for (int j = 0; j < 8; j++) acc[i][j] = 0.f;

    for (int k = 0; k < 128; k += 4) {
        float4 a[8];
#pragma unroll
        for (int i = 0; i < 8; i++) a[i] = *(const float4*)&As[m0 + i][k];
#pragma unroll
        for (int kk = 0; kk < 4; kk++) {
            float4 wa = *(const float4*)&Ws[k + kk][c0];
            float4 wb = *(const float4*)&Ws[k + kk][c0 + 4];
            float wv0 = wa.x, wv1 = wa.y, wv2 = wa.z, wv3 = wa.w;
            float wv4 = wb.x, wv5 = wb.y, wv6 = wb.z, wv7 = wb.w;
#pragma unroll
            for (int i = 0; i < 8; i++) {
                float av = ((const float*)&a[i])[kk];
                acc[i][0] = fmaf(av, wv0, acc[i][0]);
                acc[i][1] = fmaf(av, wv1, acc[i][1]);
                acc[i][2] = fmaf(av, wv2, acc[i][2]);
                acc[i][3] = fmaf(av, wv3, acc[i][3]);
                acc[i][4] = fmaf(av, wv4, acc[i][4]);
                acc[i][5] = fmaf(av, wv5, acc[i][5]);
                acc[i][6] = fmaf(av, wv6, acc[i][6]);
                acc[i][7] = fmaf(av, wv7, acc[i][7]);
            }
        }
    }

    float bj[8];
#pragma unroll
    for (int j = 0; j < 8; j++) bj[j] = bias[c0 + j];

#pragma unroll
    for (int i = 0; i < 8; i++) {
        int r = r0 + m0 + i;
        if (r >= M) continue;
        float pre  = pre_deg  ? rsqrtf((float)max(pre_deg [r], 1)) : 1.f;
        float post = post_deg ? rsqrtf((float)max(post_deg[r], 1)) : 1.f;
        float4 o0, o1;
        o0.x = fmaxf(fmaf(acc[i][0], pre, bj[0]), 0.f) * post;
        o0.y = fmaxf(fmaf(acc[i][1], pre, bj[1]), 0.f) * post;
        o0.z = fmaxf(fmaf(acc[i][2], pre, bj[2]), 0.f) * post;
        o0.w = fmaxf(fmaf(acc[i][3], pre, bj[3]), 0.f) * post;
        o1.x = fmaxf(fmaf(acc[i][4], pre, bj[4]), 0.f) * post;
        o1.y = fmaxf(fmaf(acc[i][5], pre, bj[5]), 0.f) * post;
        o1.z = fmaxf(fmaf(acc[i][6], pre, bj[6]), 0.f) * post;
        o1.w = fmaxf(fmaf(acc[i][7], pre, bj[7]), 0.f) * post;
        *(float4*)&out[(long)r * 128 + c0]     = o0;
        *(float4*)&out[(long)r * 128 + c0 + 4] = o1;
    }
}

// ---------------- final small GEMM: [1024,128] @ [128,47] with indeg norm + bias ----------------
__global__ void gemm2_k(const float* __restrict__ agg2, const float* __restrict__ W2,
                        const float* __restrict__ b2, const int* __restrict__ indeg2,
                        float* __restrict__ out) {
    __shared__ float As[128];
    int row = blockIdx.x;
    int t = threadIdx.x;   // 64 threads
    As[t]      = agg2[row * 128 + t];
    As[t + 64] = agg2[row * 128 + t + 64];
    __syncthreads();
    if (t < NCLS) {
        float acc = 0.f;
#pragma unroll
        for (int k = 0; k < 128; k++) acc = fmaf(As[k], W2[k * NCLS + t], acc);
        float rs = rsqrtf((float)max(indeg2[row], 1));
        out[row * NCLS + t] = fmaf(acc, rs, b2[t]);
    }
}

// ---------------- launcher ----------------
extern "C" void kernel_launch(void* const* d_in, const int* in_sizes, int n_in,
                              void* d_out, int out_size) {
    const float* feats = (const float*)d_in[0];
    const int* src0 = (const int*)d_in[1];
    const int* dst0 = (const int*)d_in[2];
    const int* src1 = (const int*)d_in[3];
    const int* dst1 = (const int*)d_in[4];
    const int* src2 = (const int*)d_in[5];
    const int* dst2 = (const int*)d_in[6];
    const int* invp = (const int*)d_in[7];
    const int* shufp = (const int*)d_in[8];
    const float* W0 = (const float*)d_in[9];
    const float* b0 = (const float*)d_in[10];
    const float* W1 = (const float*)d_in[11];
    const float* b1 = (const float*)d_in[12];
    const float* W2 = (const float*)d_in[13];
    const float* b2 = (const float*)d_in[14];
    float* out = (float*)d_out;

    float *agg0, *h0, *agg1, *h1, *agg2;
    int *od1, *id1, *od2, *id2;
    cudaGetSymbolAddress((void**)&agg0, g_agg0);
    cudaGetSymbolAddress((void**)&h0,   g_h0);
    cudaGetSymbolAddress((void**)&agg1, g_agg1);
    cudaGetSymbolAddress((void**)&h1,   g_h1);
    cudaGetSymbolAddress((void**)&agg2, g_agg2);
    cudaGetSymbolAddress((void**)&od1,  g_outdeg1);
    cudaGetSymbolAddress((void**)&id1,  g_indeg1);
    cudaGetSymbolAddress((void**)&od2,  g_outdeg2);
    cudaGetSymbolAddress((void**)&id2,  g_indeg2);

    const int SMEM = (128 * 132 + 128 * 128) * 4;  // 133120 B
    cudaFuncSetAttribute(gemm_k, cudaFuncAttributeMaxDynamicSharedMemorySize, SMEM);

    // zero scratch
    zero_agg0_k<<<(N_DST0 * D / 4 + 255) / 256, 256>>>();
    zero_aux_k<<<1378, 256>>>();
    // degrees for layers 1 & 2
    deg_k<<<(E1 + 255) / 256, 256>>>(src1, dst1, src2, dst2);

    // layer 0: aggregate raw feats (norm='none'), then GEMM + perm + bias + relu,
    // with next layer's out-degree scaling folded in.
    scatter_k<<<(E0 * 32 + 255) / 256, 256>>>(feats, src0, dst0, agg0, E0);
    gemm_k<<<(N_DST0 + 127) / 128, 256, SMEM>>>(agg0, W0, b0, invp, shufp,
                                                nullptr, od1, h0, N_DST0);

    // layer 1: aggregate (out-deg scale already folded into h0), GEMM with in-deg
    // scale + bias + relu, fold layer-2 out-degree scaling.
    scatter_k<<<(E1 * 32 + 255) / 256, 256>>>(h0, src1, dst1, agg1, E1);
    gemm_k<<<(N_DST1 + 127) / 128, 256, SMEM>>>(agg1, W1, b1, nullptr, nullptr,
                                                id1, od2, h1, N_DST1);

    // layer 2: aggregate, final small GEMM with in-deg scale + bias (no relu).
    scatter_k<<<(E2 * 32 + 255) / 256, 256>>>(h1, src2, dst2, agg2, E2);
    gemm2_k<<<N_DST2, 64>>>(agg2, W2, b2, id2, out);
}